// round 14
// baseline (speedup 1.0000x reference)
#include <cuda_runtime.h>
#include <cstdint>

#define TSTEPS 2048
#define NBATCH 64
#define ISZ 256
#define HSZ 256
#define G4SZ 1024

// 512 MB scratch for x_gates = input @ W_ih^T + b_ih + b_hh  (T,B,4H)
__device__ float g_xg[(size_t)TSTEPS * NBATCH * G4SZ];

// ---------- packed f32x2 helpers ----------
__device__ __forceinline__ unsigned long long pack2(float x, float y) {
    unsigned long long r;
    asm("mov.b64 %0, {%1, %2};" : "=l"(r) : "f"(x), "f"(y));
    return r;
}
__device__ __forceinline__ unsigned long long fma2(unsigned long long a,
                                                   unsigned long long b,
                                                   unsigned long long c) {
    unsigned long long d;
    asm("fma.rn.f32x2 %0, %1, %2, %3;" : "=l"(d) : "l"(a), "l"(b), "l"(c));
    return d;
}
__device__ __forceinline__ unsigned long long add2(unsigned long long a,
                                                   unsigned long long b) {
    unsigned long long d;
    asm("add.rn.f32x2 %0, %1, %2;" : "=l"(d) : "l"(a), "l"(b));
    return d;
}
__device__ __forceinline__ float2 unpack2(unsigned long long v) {
    float2 r;
    asm("mov.b64 {%0, %1}, %2;" : "=f"(r.x), "=f"(r.y) : "l"(v));
    return r;
}

__device__ __forceinline__ float sigf(float x) {
    return __fdividef(1.f, 1.f + __expf(-x));
}
__device__ __forceinline__ float tanhfastf(float x) {
    return 2.f * __fdividef(1.f, 1.f + __expf(-2.f * x)) - 1.f;
}

// ============================================================
// Kernel A: x_gates GEMM.  C[M=131072, N=1024] = A[M,256] @ W[N,256]^T + bias
// 128x128 tiles, BK=16, 256 threads, 8x8 micro-tile.
// A tile stored PRE-DUPLICATED as float2(v,v): the inner loop's broadcast
// operand comes from one LDS.64, no pack-MOVs -> fma2-issue-bound.
// ============================================================
#define BM 128
#define BN 128
#define BK 16
#define A2STR 129   // float2 stride per kk-row (bank-spread)
#define BSTR 132    // float stride per kk-row

__global__ __launch_bounds__(256, 1) void xg_gemm(
    const float* __restrict__ A, const float* __restrict__ W,
    const float* __restrict__ b1, const float* __restrict__ b2)
{
    __shared__ __align__(16) float2 As2[BK * A2STR];  // [kk][m] duplicated
    __shared__ __align__(16) float  Bs[BK * BSTR];    // [kk][n]
    int tid = threadIdx.x;
    int tx = tid & 15, ty = tid >> 4;
    size_t mBase = (size_t)blockIdx.x * BM;
    int nBase = blockIdx.y * BN;

    unsigned long long z = pack2(0.f, 0.f);
    unsigned long long acc[8][4];
#pragma unroll
    for (int i = 0; i < 8; i++)
#pragma unroll
        for (int j = 0; j < 4; j++) acc[i][j] = z;

    for (int kt = 0; kt < ISZ; kt += BK) {
        // A tile: 128 rows x 16 k = 512 float4 loads, 2 per thread,
        // stored duplicated+transposed: As2[kq*4+j][m] = (v[j], v[j])
#pragma unroll
        for (int half = 0; half < 2; half++) {
            int it = tid + half * 256;
            int m = it >> 2, kq = it & 3;
            float4 v = *(const float4*)(A + (mBase + m) * ISZ + kt + kq * 4);
            As2[(kq * 4 + 0) * A2STR + m] = make_float2(v.x, v.x);
            As2[(kq * 4 + 1) * A2STR + m] = make_float2(v.y, v.y);
            As2[(kq * 4 + 2) * A2STR + m] = make_float2(v.z, v.z);
            As2[(kq * 4 + 3) * A2STR + m] = make_float2(v.w, v.w);
        }
        // B tile: 128 rows x 16 k, transposed [kk][n]
#pragma unroll
        for (int half = 0; half < 2; half++) {
            int it = tid + half * 256;
            int n = it >> 2, kq = it & 3;
            float4 v = *(const float4*)(W + (size_t)(nBase + n) * ISZ + kt + kq * 4);
            Bs[(kq * 4 + 0) * BSTR + n] = v.x;
            Bs[(kq * 4 + 1) * BSTR + n] = v.y;
            Bs[(kq * 4 + 2) * BSTR + n] = v.z;
            Bs[(kq * 4 + 3) * BSTR + n] = v.w;
        }
        __syncthreads();
#pragma unroll
        for (int kk = 0; kk < BK; kk++) {
            // b: 8 cols -> 4 packed pairs
            float4 b0 = *(const float4*)(Bs + kk * BSTR + tx * 8);
            float4 b1v = *(const float4*)(Bs + kk * BSTR + tx * 8 + 4);
            unsigned long long bp[4];
            bp[0] = pack2(b0.x, b0.y);
            bp[1] = pack2(b0.z, b0.w);
            bp[2] = pack2(b1v.x, b1v.y);
            bp[3] = pack2(b1v.z, b1v.w);
            // a: 8 rows, each one LDS.64 of (v,v)
            const float2* ap = As2 + kk * A2STR + ty * 8;
#pragma unroll
            for (int i = 0; i < 8; i++) {
                unsigned long long a2 =
                    *(const unsigned long long*)(ap + i);
#pragma unroll
                for (int j = 0; j < 4; j++)
                    acc[i][j] = fma2(a2, bp[j], acc[i][j]);
            }
        }
        __syncthreads();
    }
    int n0 = nBase + tx * 8;
    float bias[8];
#pragma unroll
    for (int j = 0; j < 8; j++) bias[j] = b1[n0 + j] + b2[n0 + j];
#pragma unroll
    for (int i = 0; i < 8; i++) {
        float2 p0 = unpack2(acc[i][0]);
        float2 p1 = unpack2(acc[i][1]);
        float2 p2 = unpack2(acc[i][2]);
        float2 p3 = unpack2(acc[i][3]);
        float* orow = g_xg + (mBase + ty * 8 + i) * G4SZ + n0;
        *(float4*)(orow) = make_float4(p0.x + bias[0], p0.y + bias[1],
                                       p1.x + bias[2], p1.y + bias[3]);
        *(float4*)(orow + 4) = make_float4(p2.x + bias[4], p2.y + bias[5],
                                           p3.x + bias[6], p3.y + bias[7]);
    }
}

// ============================================================
// Kernel B: recurrence (round-9 champion, verbatim).
// 8 clusters x 8 CTAs, 512 thr/CTA; two pipelined 4-batch groups.
// ============================================================
#define OUT_HT ((size_t)TSTEPS * NBATCH * HSZ)
#define OUT_CT (OUT_HT + (size_t)NBATCH * HSZ)
#define HX_BYTES 4096   // 8 CTAs * 512B received per step per group

// recurrent GEMM partials for one group: 4 batches, K-quarter qk
__device__ __forceinline__ void rec_gemm(
    const float* __restrict__ hbuf, float* __restrict__ red,
    const unsigned long long* __restrict__ w2, int qk, int lr,
    unsigned long long z)
{
    float gsum[4];
#pragma unroll
    for (int b = 0; b < 4; b++) {
        unsigned long long a = z, c = z;
#pragma unroll
        for (int kb = 0; kb < 2; kb++) {
            const ulonglong2* hp = (const ulonglong2*)(
                hbuf + (2 * qk + kb) * 128 + b * 32);
#pragma unroll
            for (int i = 0; i < 8; i++) {
                ulonglong2 hv = hp[i];
                a = fma2(w2[kb * 16 + 2 * i + 0], hv.x, a);
                c = fma2(w2[kb * 16 + 2 * i + 1], hv.y, c);
            }
        }
        float2 p = unpack2(add2(a, c));
        gsum[b] = p.x + p.y;
    }
#pragma unroll
    for (int b = 0; b < 4; b++)
        red[(qk * 4 + b) * 128 + lr] = gsum[b];
}

#define MBAR_WAIT(mb, ph)                                                      \
    asm volatile(                                                              \
        "{\n\t.reg .pred P;\n\t"                                               \
        "LW_%=:\n\t"                                                           \
        "mbarrier.try_wait.parity.acquire.cta.shared::cta.b64 P, [%0], %1, 0x989680;\n\t" \
        "@P bra.uni LD_%=;\n\t"                                                \
        "bra.uni LW_%=;\n\t"                                                   \
        "LD_%=:\n\t}" :: "r"(mb), "r"(ph) : "memory")

__global__ void __cluster_dims__(8, 1, 1) __launch_bounds__(512, 1) lstm_rec(
    const float* __restrict__ h0, const float* __restrict__ c0,
    const float* __restrict__ Whh, float* __restrict__ out, int write_tail)
{
    __shared__ __align__(16) float hsmA[2 * 1024];
    __shared__ __align__(16) float hsmB[2 * 1024];
    __shared__ __align__(16) float redA[4 * 4 * 128];
    __shared__ __align__(16) float redB[4 * 4 * 128];
    __shared__ __align__(16) float stageA[128];
    __shared__ __align__(16) float stageB[128];
    __shared__ __align__(8) unsigned long long mbars[4]; // A0 A1 B0 B1

    int tid = threadIdx.x;
    unsigned crank;
    asm("mov.u32 %0, %%cluster_ctarank;" : "=r"(crank));
    int cid = blockIdx.x >> 3;
    int b0A = cid * 8;
    int b0B = b0A + 4;

    int qk = tid >> 7, lr = tid & 127;
    int gr = (lr >> 5) * 256 + (int)crank * 32 + (lr & 31);  // global gate row

    uint32_t mbA0 = (uint32_t)__cvta_generic_to_shared(&mbars[0]);
    uint32_t mbA1 = (uint32_t)__cvta_generic_to_shared(&mbars[1]);
    uint32_t mbB0 = (uint32_t)__cvta_generic_to_shared(&mbars[2]);
    uint32_t mbB1 = (uint32_t)__cvta_generic_to_shared(&mbars[3]);

    // ---- W_hh slice -> registers, pre-paired for f32x2 (shared A/B) ----
    unsigned long long w2[32];
    {
        const float* wp = Whh + (size_t)gr * HSZ + qk * 64;
#pragma unroll
        for (int i = 0; i < 16; i++) {
            float4 v = *(const float4*)(wp + i * 4);
            w2[i * 2 + 0] = pack2(v.x, v.y);
            w2[i * 2 + 1] = pack2(v.z, v.w);
        }
    }
    // ---- init h buffer 0 for both groups ----
    for (int it = tid; it < 1024; it += 512) {
        int blk = it >> 7, b = (it >> 5) & 3, co = it & 31;
        hsmA[it] = h0[(size_t)(b0A + b) * HSZ + blk * 32 + co];
        hsmB[it] = h0[(size_t)(b0B + b) * HSZ + blk * 32 + co];
    }
    // ---- elementwise state (tid<128): (batch eb, col eco) ----
    int eb = tid >> 5, eco = tid & 31;
    int ecol = (int)crank * 32 + eco;
    float cregA = 0.f, cregB = 0.f;
    if (tid < 128) {
        cregA = c0[(size_t)(b0A + eb) * HSZ + ecol];
        cregB = c0[(size_t)(b0B + eb) * HSZ + ecol];
    }

    // ---- mbarrier init + arm ----
    if (tid == 0) {
#pragma unroll
        for (int i = 0; i < 4; i++) {
            uint32_t mb = (uint32_t)__cvta_generic_to_shared(&mbars[i]);
            asm volatile("mbarrier.init.shared.b64 [%0], 1;" :: "r"(mb) : "memory");
        }
    }
    __syncthreads();
    if (tid == 0) {
#pragma unroll
        for (int i = 0; i < 4; i++) {
            uint32_t mb = (uint32_t)__cvta_generic_to_shared(&mbars[i]);
            asm volatile("mbarrier.arrive.expect_tx.shared.b64 _, [%0], %1;"
                         :: "r"(mb), "r"(HX_BYTES) : "memory");
        }
    }
    __syncthreads();
    // all cluster CTAs' barriers live before any peer st.async
    asm volatile("barrier.cluster.arrive.aligned;" ::: "memory");
    asm volatile("barrier.cluster.wait.aligned;" ::: "memory");

    unsigned long long z = pack2(0.f, 0.f);
    int phA0 = 0, phA1 = 0, phB0 = 0, phB1 = 0;

    for (int t = 0; t < TSTEPS; t++) {
        int cur = t & 1, nxt = cur ^ 1;

        // ---------------- group A ----------------
        float xg0 = 0.f, xg1 = 0.f, xg2 = 0.f, xg3 = 0.f;
        if (tid < 128) {
            const float* xp = g_xg + ((size_t)t * NBATCH + b0A + eb) * G4SZ + ecol;
            xg0 = xp[0]; xg1 = xp[256]; xg2 = xp[512]; xg3 = xp[768];
        }
        if (t > 0) {
            uint32_t mb = cur ? mbA1 : mbA0;
            int ph = cur ? phA1 : phA0;
            MBAR_WAIT(mb, ph);
            if (cur) phA1 ^= 1; else phA0 ^= 1;
            if (tid == 0)
                asm volatile("mbarrier.arrive.expect_tx.shared.b64 _, [%0], %1;"
                             :: "r"(mb), "r"(HX_BYTES) : "memory");
        }
        rec_gemm(hsmA + cur * 1024, redA, w2, qk, lr, z);
        __syncthreads();

        float xb0 = 0.f, xb1 = 0.f, xb2 = 0.f, xb3 = 0.f;
        if (tid < 128) {
            // prefetch group-B x_gates early (hidden under EW_A + GEMM_B)
            const float* xq = g_xg + ((size_t)t * NBATCH + b0B + eb) * G4SZ + ecol;
            xb0 = xq[0]; xb1 = xq[256]; xb2 = xq[512]; xb3 = xq[768];

            float gs[4];
#pragma unroll
            for (int g = 0; g < 4; g++) {
                int row = g * 32 + eco;
                gs[g] = redA[(0 * 4 + eb) * 128 + row]
                      + redA[(1 * 4 + eb) * 128 + row]
                      + redA[(2 * 4 + eb) * 128 + row]
                      + redA[(3 * 4 + eb) * 128 + row];
            }
            float iv = sigf(gs[0] + xg0);
            float fv = sigf(gs[1] + xg1);
            float gv = tanhfastf(gs[2] + xg2);
            float ov = sigf(gs[3] + xg3);
            cregA = fv * cregA + iv * gv;
            float hn = ov * tanhfastf(cregA);

            out[((size_t)t * NBATCH + b0A + eb) * HSZ + ecol] = hn;
            if (t < TSTEPS - 1) {
                stageA[eb * 32 + eco] = hn;
                asm volatile("bar.sync 1, 128;" ::: "memory");
                if (tid < 32) {
                    uint4 v = *(const uint4*)(stageA + tid * 4);
                    uint32_t ldst = (uint32_t)__cvta_generic_to_shared(
                        hsmA + nxt * 1024 + (int)crank * 128 + tid * 4);
                    uint32_t lmb = nxt ? mbA1 : mbA0;
#pragma unroll
                    for (int p = 0; p < 8; p++) {
                        uint32_t rdst, rmb;
                        asm volatile("mapa.shared::cluster.u32 %0, %1, %2;"
                                     : "=r"(rdst) : "r"(ldst), "r"(p));
                        asm volatile("mapa.shared::cluster.u32 %0, %1, %2;"
                                     : "=r"(rmb) : "r"(lmb), "r"(p));
                        asm volatile(
                            "st.async.shared::cluster.mbarrier::complete_tx::bytes.v4.b32 "
                            "[%0], {%1, %2, %3, %4}, [%5];"
                            :: "r"(rdst), "r"(v.x), "r"(v.y), "r"(v.z), "r"(v.w),
                               "r"(rmb) : "memory");
                    }
                }
            } else if (write_tail) {
                out[OUT_HT + (size_t)(b0A + eb) * HSZ + ecol] = hn;
                out[OUT_CT + (size_t)(b0A + eb) * HSZ + ecol] = cregA;
            }
        }

        // ---------------- group B ----------------
        if (t > 0) {
            uint32_t mb = cur ? mbB1 : mbB0;
            int ph = cur ? phB1 : phB0;
            MBAR_WAIT(mb, ph);
            if (cur) phB1 ^= 1; else phB0 ^= 1;
            if (tid == 0)
                asm volatile("mbarrier.arrive.expect_tx.shared.b64 _, [%0], %1;"
                             :: "r"(mb), "r"(HX_BYTES) : "memory");
        }
        rec_gemm(hsmB + cur * 1024, redB, w2, qk, lr, z);
        __syncthreads();

        if (tid < 128) {
            float gs[4];
#pragma unroll
            for (int g = 0; g < 4; g++) {
                int row = g * 32 + eco;
                gs[g] = redB[(0 * 4 + eb) * 128 + row]
                      + redB[(1 * 4 + eb) * 128 + row]
                      + redB[(2 * 4 + eb) * 128 + row]
                      + redB[(3 * 4 + eb) * 128 + row];
            }
            float iv = sigf(gs[0] + xb0);
            float fv = sigf(gs[1] + xb1);
            float gv = tanhfastf(gs[2] + xb2);
            float ov = sigf(gs[3] + xb3);
            cregB = fv * cregB + iv * gv;
            float hn = ov * tanhfastf(cregB);

            out[((size_t)t * NBATCH + b0B + eb) * HSZ + ecol] = hn;
            if (t < TSTEPS - 1) {
                stageB[eb * 32 + eco] = hn;
                asm volatile("bar.sync 1, 128;" ::: "memory");
                if (tid < 32) {
                    uint4 v = *(const uint4*)(stageB + tid * 4);
                    uint32_t ldst = (uint32_t)__cvta_generic_to_shared(
                        hsmB + nxt * 1024 + (int)crank * 128 + tid * 4);
                    uint32_t lmb = nxt ? mbB1 : mbB0;
#pragma unroll
                    for (int p = 0; p < 8; p++) {
                        uint32_t rdst, rmb;
                        asm volatile("mapa.shared::cluster.u32 %0, %1, %2;"
                                     : "=r"(rdst) : "r"(ldst), "r"(p));
                        asm volatile("mapa.shared::cluster.u32 %0, %1, %2;"
                                     : "=r"(rmb) : "r"(lmb), "r"(p));
                        asm volatile(
                            "st.async.shared::cluster.mbarrier::complete_tx::bytes.v4.b32 "
                            "[%0], {%1, %2, %3, %4}, [%5];"
                            :: "r"(rdst), "r"(v.x), "r"(v.y), "r"(v.z), "r"(v.w),
                               "r"(rmb) : "memory");
                    }
                }
            } else if (write_tail) {
                out[OUT_HT + (size_t)(b0B + eb) * HSZ + ecol] = hn;
                out[OUT_CT + (size_t)(b0B + eb) * HSZ + ecol] = cregB;
            }
        }
    }
}

// ============================================================
extern "C" void kernel_launch(void* const* d_in, const int* in_sizes, int n_in,
                              void* d_out, int out_size) {
    const float* input = (const float*)d_in[0];
    const float* h0    = (const float*)d_in[1];
    const float* c0    = (const float*)d_in[2];
    const float* W_ih  = (const float*)d_in[3];
    const float* W_hh  = (const float*)d_in[4];
    const float* b_ih  = (const float*)d_in[5];
    const float* b_hh  = (const float*)d_in[6];
    float* out = (float*)d_out;

    int write_tail = (out_size >= (int)(OUT_CT + (size_t)NBATCH * HSZ)) ? 1 : 0;

    dim3 gA((TSTEPS * NBATCH) / BM, G4SZ / BN);
    xg_gemm<<<gA, 256>>>(input, W_ih, b_ih, b_hh);

    lstm_rec<<<64, 512>>>(h0, c0, W_hh, out, write_tail);
}

// round 15
// speedup vs baseline: 1.1367x; 1.1367x over previous
#include <cuda_runtime.h>
#include <cstdint>

#define TSTEPS 2048
#define NBATCH 64
#define ISZ 256
#define HSZ 256
#define G4SZ 1024

// 512 MB scratch for x_gates = input @ W_ih^T + b_ih + b_hh  (T,B,4H)
__device__ float g_xg[(size_t)TSTEPS * NBATCH * G4SZ];
// per-m-tile progress: 16 N-tiles each; one m covers 2 timesteps
__device__ int g_prog[1024];

// ---------- packed f32x2 helpers ----------
__device__ __forceinline__ unsigned long long pack2(float x, float y) {
    unsigned long long r;
    asm("mov.b64 %0, {%1, %2};" : "=l"(r) : "f"(x), "f"(y));
    return r;
}
__device__ __forceinline__ unsigned long long fma2(unsigned long long a,
                                                   unsigned long long b,
                                                   unsigned long long c) {
    unsigned long long d;
    asm("fma.rn.f32x2 %0, %1, %2, %3;" : "=l"(d) : "l"(a), "l"(b), "l"(c));
    return d;
}
__device__ __forceinline__ unsigned long long add2(unsigned long long a,
                                                   unsigned long long b) {
    unsigned long long d;
    asm("add.rn.f32x2 %0, %1, %2;" : "=l"(d) : "l"(a), "l"(b));
    return d;
}
__device__ __forceinline__ float2 unpack2(unsigned long long v) {
    float2 r;
    asm("mov.b64 {%0, %1}, %2;" : "=f"(r.x), "=f"(r.y) : "l"(v));
    return r;
}

__device__ __forceinline__ float sigf(float x) {
    return __fdividef(1.f, 1.f + __expf(-x));
}
__device__ __forceinline__ float tanhfastf(float x) {
    return 2.f * __fdividef(1.f, 1.f + __expf(-2.f * x)) - 1.f;
}

__global__ void zero_prog() { g_prog[threadIdx.x] = 0; }

// ============================================================
// Kernel A: x_gates GEMM (round-1 version, 1.42ms) + progress publish.
// C[M=131072, N=1024] = A[M,256] @ W[N,256]^T + bias
// ============================================================
#define BM 128
#define BN 64
#define BK 16
#define ASTR 132
#define BSTR 68

__global__ __launch_bounds__(256) void xg_gemm(
    const float* __restrict__ A, const float* __restrict__ W,
    const float* __restrict__ b1, const float* __restrict__ b2)
{
    __shared__ float As[BK * ASTR];  // [k][m]
    __shared__ float Bs[BK * BSTR];  // [k][n]
    int tid = threadIdx.x;
    int tx = tid & 15, ty = tid >> 4;
    size_t mBase = (size_t)blockIdx.x * BM;
    int nBase = blockIdx.y * BN;

    unsigned long long z = pack2(0.f, 0.f);
    unsigned long long acc[8][2];
#pragma unroll
    for (int i = 0; i < 8; i++) { acc[i][0] = z; acc[i][1] = z; }

    for (int kt = 0; kt < ISZ; kt += BK) {
#pragma unroll
        for (int it = tid; it < (BM * BK / 4); it += 256) {
            int m = it >> 2, kq = it & 3;
            float4 v = *(const float4*)(A + (mBase + m) * ISZ + kt + kq * 4);
            As[(kq * 4 + 0) * ASTR + m] = v.x;
            As[(kq * 4 + 1) * ASTR + m] = v.y;
            As[(kq * 4 + 2) * ASTR + m] = v.z;
            As[(kq * 4 + 3) * ASTR + m] = v.w;
        }
        {
            int n = tid >> 2, kq = tid & 3;
            float4 v = *(const float4*)(W + (size_t)(nBase + n) * ISZ + kt + kq * 4);
            Bs[(kq * 4 + 0) * BSTR + n] = v.x;
            Bs[(kq * 4 + 1) * BSTR + n] = v.y;
            Bs[(kq * 4 + 2) * BSTR + n] = v.z;
            Bs[(kq * 4 + 3) * BSTR + n] = v.w;
        }
        __syncthreads();
#pragma unroll
        for (int kk = 0; kk < BK; kk++) {
            float4 a0 = *(const float4*)(As + kk * ASTR + ty * 8);
            float4 a1 = *(const float4*)(As + kk * ASTR + ty * 8 + 4);
            float4 bv = *(const float4*)(Bs + kk * BSTR + tx * 4);
            unsigned long long bp0 = pack2(bv.x, bv.y);
            unsigned long long bp1 = pack2(bv.z, bv.w);
            float am[8] = {a0.x, a0.y, a0.z, a0.w, a1.x, a1.y, a1.z, a1.w};
#pragma unroll
            for (int i = 0; i < 8; i++) {
                unsigned long long ap = pack2(am[i], am[i]);
                acc[i][0] = fma2(ap, bp0, acc[i][0]);
                acc[i][1] = fma2(ap, bp1, acc[i][1]);
            }
        }
        __syncthreads();
    }
    int n0 = nBase + tx * 4;
    float bx = b1[n0 + 0] + b2[n0 + 0];
    float by = b1[n0 + 1] + b2[n0 + 1];
    float bz = b1[n0 + 2] + b2[n0 + 2];
    float bw = b1[n0 + 3] + b2[n0 + 3];
#pragma unroll
    for (int i = 0; i < 8; i++) {
        float2 p0 = unpack2(acc[i][0]);
        float2 p1 = unpack2(acc[i][1]);
        float4 o = make_float4(p0.x + bx, p0.y + by, p1.x + bz, p1.y + bw);
        *(float4*)(g_xg + (mBase + ty * 8 + i) * G4SZ + n0) = o;
    }
    // publish: this (m, n-tile) is complete
    __threadfence();
    __syncthreads();
    if (tid == 0) atomicAdd(&g_prog[blockIdx.x], 1);
}

// ============================================================
// Kernel B: recurrence (round-9 champion) + x_gates progress acquire.
// 8 clusters x 8 CTAs, 512 thr/CTA; two pipelined 4-batch groups.
// ============================================================
#define OUT_HT ((size_t)TSTEPS * NBATCH * HSZ)
#define OUT_CT (OUT_HT + (size_t)NBATCH * HSZ)
#define HX_BYTES 4096   // 8 CTAs * 512B received per step per group

// recurrent GEMM partials for one group: 4 batches, K-quarter qk
__device__ __forceinline__ void rec_gemm(
    const float* __restrict__ hbuf, float* __restrict__ red,
    const unsigned long long* __restrict__ w2, int qk, int lr,
    unsigned long long z)
{
    float gsum[4];
#pragma unroll
    for (int b = 0; b < 4; b++) {
        unsigned long long a = z, c = z;
#pragma unroll
        for (int kb = 0; kb < 2; kb++) {
            const ulonglong2* hp = (const ulonglong2*)(
                hbuf + (2 * qk + kb) * 128 + b * 32);
#pragma unroll
            for (int i = 0; i < 8; i++) {
                ulonglong2 hv = hp[i];
                a = fma2(w2[kb * 16 + 2 * i + 0], hv.x, a);
                c = fma2(w2[kb * 16 + 2 * i + 1], hv.y, c);
            }
        }
        float2 p = unpack2(add2(a, c));
        gsum[b] = p.x + p.y;
    }
#pragma unroll
    for (int b = 0; b < 4; b++)
        red[(qk * 4 + b) * 128 + lr] = gsum[b];
}

#define MBAR_WAIT(mb, ph)                                                      \
    asm volatile(                                                              \
        "{\n\t.reg .pred P;\n\t"                                               \
        "LW_%=:\n\t"                                                           \
        "mbarrier.try_wait.parity.acquire.cta.shared::cta.b64 P, [%0], %1, 0x989680;\n\t" \
        "@P bra.uni LD_%=;\n\t"                                                \
        "bra.uni LW_%=;\n\t"                                                   \
        "LD_%=:\n\t}" :: "r"(mb), "r"(ph) : "memory")

__global__ void __cluster_dims__(8, 1, 1) __launch_bounds__(512, 1) lstm_rec(
    const float* __restrict__ h0, const float* __restrict__ c0,
    const float* __restrict__ Whh, float* __restrict__ out, int write_tail)
{
    __shared__ __align__(16) float hsmA[2 * 1024];
    __shared__ __align__(16) float hsmB[2 * 1024];
    __shared__ __align__(16) float redA[4 * 4 * 128];
    __shared__ __align__(16) float redB[4 * 4 * 128];
    __shared__ __align__(16) float stageA[128];
    __shared__ __align__(16) float stageB[128];
    __shared__ __align__(8) unsigned long long mbars[4]; // A0 A1 B0 B1

    int tid = threadIdx.x;
    unsigned crank;
    asm("mov.u32 %0, %%cluster_ctarank;" : "=r"(crank));
    int cid = blockIdx.x >> 3;
    int b0A = cid * 8;
    int b0B = b0A + 4;

    int qk = tid >> 7, lr = tid & 127;
    int gr = (lr >> 5) * 256 + (int)crank * 32 + (lr & 31);  // global gate row

    uint32_t mbA0 = (uint32_t)__cvta_generic_to_shared(&mbars[0]);
    uint32_t mbA1 = (uint32_t)__cvta_generic_to_shared(&mbars[1]);
    uint32_t mbB0 = (uint32_t)__cvta_generic_to_shared(&mbars[2]);
    uint32_t mbB1 = (uint32_t)__cvta_generic_to_shared(&mbars[3]);

    // ---- W_hh slice -> registers, pre-paired for f32x2 (shared A/B) ----
    unsigned long long w2[32];
    {
        const float* wp = Whh + (size_t)gr * HSZ + qk * 64;
#pragma unroll
        for (int i = 0; i < 16; i++) {
            float4 v = *(const float4*)(wp + i * 4);
            w2[i * 2 + 0] = pack2(v.x, v.y);
            w2[i * 2 + 1] = pack2(v.z, v.w);
        }
    }
    // ---- init h buffer 0 for both groups ----
    for (int it = tid; it < 1024; it += 512) {
        int blk = it >> 7, b = (it >> 5) & 3, co = it & 31;
        hsmA[it] = h0[(size_t)(b0A + b) * HSZ + blk * 32 + co];
        hsmB[it] = h0[(size_t)(b0B + b) * HSZ + blk * 32 + co];
    }
    // ---- elementwise state (tid<128): (batch eb, col eco) ----
    int eb = tid >> 5, eco = tid & 31;
    int ecol = (int)crank * 32 + eco;
    float cregA = 0.f, cregB = 0.f;
    if (tid < 128) {
        cregA = c0[(size_t)(b0A + eb) * HSZ + ecol];
        cregB = c0[(size_t)(b0B + eb) * HSZ + ecol];
    }

    // ---- mbarrier init + arm ----
    if (tid == 0) {
#pragma unroll
        for (int i = 0; i < 4; i++) {
            uint32_t mb = (uint32_t)__cvta_generic_to_shared(&mbars[i]);
            asm volatile("mbarrier.init.shared.b64 [%0], 1;" :: "r"(mb) : "memory");
        }
    }
    __syncthreads();
    if (tid == 0) {
#pragma unroll
        for (int i = 0; i < 4; i++) {
            uint32_t mb = (uint32_t)__cvta_generic_to_shared(&mbars[i]);
            asm volatile("mbarrier.arrive.expect_tx.shared.b64 _, [%0], %1;"
                         :: "r"(mb), "r"(HX_BYTES) : "memory");
        }
    }
    __syncthreads();
    // all cluster CTAs' barriers live before any peer st.async
    asm volatile("barrier.cluster.arrive.aligned;" ::: "memory");
    asm volatile("barrier.cluster.wait.aligned;" ::: "memory");

    unsigned long long z = pack2(0.f, 0.f);
    int phA0 = 0, phA1 = 0, phB0 = 0, phB1 = 0;
    int ready_m = -1;

    for (int t = 0; t < TSTEPS; t++) {
        int cur = t & 1, nxt = cur ^ 1;

        // ---------------- group A ----------------
        float xg0 = 0.f, xg1 = 0.f, xg2 = 0.f, xg3 = 0.f;
        if (tid < 128) {
            int m = t >> 1;
            if (m > ready_m) {   // acquire producer progress (new m only)
                int v;
                do {
                    asm volatile("ld.global.acquire.gpu.b32 %0, [%1];"
                                 : "=r"(v) : "l"(g_prog + m) : "memory");
                } while (v < 16);
                ready_m = m;
            }
            const float* xp = g_xg + ((size_t)t * NBATCH + b0A + eb) * G4SZ + ecol;
            xg0 = xp[0]; xg1 = xp[256]; xg2 = xp[512]; xg3 = xp[768];
        }
        if (t > 0) {
            uint32_t mb = cur ? mbA1 : mbA0;
            int ph = cur ? phA1 : phA0;
            MBAR_WAIT(mb, ph);
            if (cur) phA1 ^= 1; else phA0 ^= 1;
            if (tid == 0)
                asm volatile("mbarrier.arrive.expect_tx.shared.b64 _, [%0], %1;"
                             :: "r"(mb), "r"(HX_BYTES) : "memory");
        }
        rec_gemm(hsmA + cur * 1024, redA, w2, qk, lr, z);
        __syncthreads();

        float xb0 = 0.f, xb1 = 0.f, xb2 = 0.f, xb3 = 0.f;
        if (tid < 128) {
            // prefetch group-B x_gates early (hidden under EW_A + GEMM_B)
            const float* xq = g_xg + ((size_t)t * NBATCH + b0B + eb) * G4SZ + ecol;
            xb0 = xq[0]; xb1 = xq[256]; xb2 = xq[512]; xb3 = xq[768];

            float gs[4];
#pragma unroll
            for (int g = 0; g < 4; g++) {
                int row = g * 32 + eco;
                gs[g] = redA[(0 * 4 + eb) * 128 + row]
                      + redA[(1 * 4 + eb) * 128 + row]
                      + redA[(2 * 4 + eb) * 128 + row]
                      + redA[(3 * 4 + eb) * 128 + row];
            }
            float iv = sigf(gs[0] + xg0);
            float fv = sigf(gs[1] + xg1);
            float gv = tanhfastf(gs[2] + xg2);
            float ov = sigf(gs[3] + xg3);
            cregA = fv * cregA + iv * gv;
            float hn = ov * tanhfastf(cregA);

            out[((size_t)t * NBATCH + b0A + eb) * HSZ + ecol] = hn;
            if (t < TSTEPS - 1) {
                stageA[eb * 32 + eco] = hn;
                asm volatile("bar.sync 1, 128;" ::: "memory");
                if (tid < 32) {
                    uint4 v = *(const uint4*)(stageA + tid * 4);
                    uint32_t ldst = (uint32_t)__cvta_generic_to_shared(
                        hsmA + nxt * 1024 + (int)crank * 128 + tid * 4);
                    uint32_t lmb = nxt ? mbA1 : mbA0;
#pragma unroll
                    for (int p = 0; p < 8; p++) {
                        uint32_t rdst, rmb;
                        asm volatile("mapa.shared::cluster.u32 %0, %1, %2;"
                                     : "=r"(rdst) : "r"(ldst), "r"(p));
                        asm volatile("mapa.shared::cluster.u32 %0, %1, %2;"
                                     : "=r"(rmb) : "r"(lmb), "r"(p));
                        asm volatile(
                            "st.async.shared::cluster.mbarrier::complete_tx::bytes.v4.b32 "
                            "[%0], {%1, %2, %3, %4}, [%5];"
                            :: "r"(rdst), "r"(v.x), "r"(v.y), "r"(v.z), "r"(v.w),
                               "r"(rmb) : "memory");
                    }
                }
            } else if (write_tail) {
                out[OUT_HT + (size_t)(b0A + eb) * HSZ + ecol] = hn;
                out[OUT_CT + (size_t)(b0A + eb) * HSZ + ecol] = cregA;
            }
        }

        // ---------------- group B ----------------
        if (t > 0) {
            uint32_t mb = cur ? mbB1 : mbB0;
            int ph = cur ? phB1 : phB0;
            MBAR_WAIT(mb, ph);
            if (cur) phB1 ^= 1; else phB0 ^= 1;
            if (tid == 0)
                asm volatile("mbarrier.arrive.expect_tx.shared.b64 _, [%0], %1;"
                             :: "r"(mb), "r"(HX_BYTES) : "memory");
        }
        rec_gemm(hsmB + cur * 1024, redB, w2, qk, lr, z);
        __syncthreads();

        if (tid < 128) {
            float gs[4];
#pragma unroll
            for (int g = 0; g < 4; g++) {
                int row = g * 32 + eco;
                gs[g] = redB[(0 * 4 + eb) * 128 + row]
                      + redB[(1 * 4 + eb) * 128 + row]
                      + redB[(2 * 4 + eb) * 128 + row]
                      + redB[(3 * 4 + eb) * 128 + row];
            }
            float iv = sigf(gs[0] + xb0);
            float fv = sigf(gs[1] + xb1);
            float gv = tanhfastf(gs[2] + xb2);
            float ov = sigf(gs[3] + xb3);
            cregB = fv * cregB + iv * gv;
            float hn = ov * tanhfastf(cregB);

            out[((size_t)t * NBATCH + b0B + eb) * HSZ + ecol] = hn;
            if (t < TSTEPS - 1) {
                stageB[eb * 32 + eco] = hn;
                asm volatile("bar.sync 1, 128;" ::: "memory");
                if (tid < 32) {
                    uint4 v = *(const uint4*)(stageB + tid * 4);
                    uint32_t ldst = (uint32_t)__cvta_generic_to_shared(
                        hsmB + nxt * 1024 + (int)crank * 128 + tid * 4);
                    uint32_t lmb = nxt ? mbB1 : mbB0;
#pragma unroll
                    for (int p = 0; p < 8; p++) {
                        uint32_t rdst, rmb;
                        asm volatile("mapa.shared::cluster.u32 %0, %1, %2;"
                                     : "=r"(rdst) : "r"(ldst), "r"(p));
                        asm volatile("mapa.shared::cluster.u32 %0, %1, %2;"
                                     : "=r"(rmb) : "r"(lmb), "r"(p));
                        asm volatile(
                            "st.async.shared::cluster.mbarrier::complete_tx::bytes.v4.b32 "
                            "[%0], {%1, %2, %3, %4}, [%5];"
                            :: "r"(rdst), "r"(v.x), "r"(v.y), "r"(v.z), "r"(v.w),
                               "r"(rmb) : "memory");
                    }
                }
            } else if (write_tail) {
                out[OUT_HT + (size_t)(b0B + eb) * HSZ + ecol] = hn;
                out[OUT_CT + (size_t)(b0B + eb) * HSZ + ecol] = cregB;
            }
        }
    }
}

// ============================================================
extern "C" void kernel_launch(void* const* d_in, const int* in_sizes, int n_in,
                              void* d_out, int out_size) {
    const float* input = (const float*)d_in[0];
    const float* h0    = (const float*)d_in[1];
    const float* c0    = (const float*)d_in[2];
    const float* W_ih  = (const float*)d_in[3];
    const float* W_hh  = (const float*)d_in[4];
    const float* b_ih  = (const float*)d_in[5];
    const float* b_hh  = (const float*)d_in[6];
    float* out = (float*)d_out;

    int write_tail = (out_size >= (int)(OUT_CT + (size_t)NBATCH * HSZ)) ? 1 : 0;

    static cudaStream_t s2 = nullptr;
    static cudaEvent_t evFork = nullptr, evJoin = nullptr;
    if (!s2) {
        cudaStreamCreateWithFlags(&s2, cudaStreamNonBlocking);
        cudaEventCreateWithFlags(&evFork, cudaEventDisableTiming);
        cudaEventCreateWithFlags(&evJoin, cudaEventDisableTiming);
    }

    // reset progress flags, then fork: gemm on s2 concurrent with rec on 0
    zero_prog<<<1, 1024>>>();
    cudaEventRecord(evFork, 0);
    cudaStreamWaitEvent(s2, evFork, 0);

    dim3 gA((TSTEPS * NBATCH) / BM, G4SZ / BN);
    xg_gemm<<<gA, 256, 0, s2>>>(input, W_ih, b_ih, b_hh);
    cudaEventRecord(evJoin, s2);

    lstm_rec<<<64, 512>>>(h0, c0, W_hh, out, write_tail);

    cudaStreamWaitEvent(0, evJoin, 0);
}